// round 5
// baseline (speedup 1.0000x reference)
#include <cuda_runtime.h>
#include <cstdint>

#define Bsz 256
#define Tn  100
#define Fn  256
#define Hn  1024
#define On  8

#define CLUSTER 4
#define CSEG    (Hn / CLUSTER)        // 256 cols per CTA
#define NTS     256                   // scan threads per CTA (1 col each)

#define ALPHA 0.9048374180359595f
#define BETA  0.8187307530779818f

// Output layout: out [B,T+1,O], s1 [B,T,H], s2 [B,T,H], v1 [B,T,H], v2 [B,T,H]
#define S1_OFF  (Bsz*(Tn+1)*On)
#define S2_OFF  (S1_OFF + Bsz*Tn*Hn)
#define V1_OFF  (S2_OFF + Bsz*Tn*Hn)
#define V2_OFF  (V1_OFF + Bsz*Tn*Hn)

__device__ float g_H1[(size_t)Bsz * Tn * Hn];   // inputs @ W0

// ---------------------------------------------------------------------------
// fp32 SGEMM (sequential-k FFMA chain, bit-matches reference association).
// ---------------------------------------------------------------------------
__global__ __launch_bounds__(256) void sgemm_kernel(
    const float* __restrict__ A, const float* __restrict__ B,
    float* __restrict__ C, int M, int N, int K)
{
    __shared__ float As[8][128];
    __shared__ float Bs[8][128];

    int tid  = threadIdx.x;
    int brow = blockIdx.y * 128;
    int bcol = blockIdx.x * 128;

    int arow = tid >> 1;
    int acol = (tid & 1) << 2;
    int brw  = tid >> 5;
    int bcl  = (tid & 31) << 2;
    int ty = (tid >> 4) << 3;
    int tx = (tid & 15) << 3;

    float acc[8][8];
#pragma unroll
    for (int i = 0; i < 8; i++)
#pragma unroll
        for (int j = 0; j < 8; j++) acc[i][j] = 0.f;

    for (int k0 = 0; k0 < K; k0 += 8) {
        float4 a4 = *(const float4*)(A + (size_t)(brow + arow) * K + k0 + acol);
        As[acol + 0][arow] = a4.x;
        As[acol + 1][arow] = a4.y;
        As[acol + 2][arow] = a4.z;
        As[acol + 3][arow] = a4.w;
        *(float4*)&Bs[brw][bcl] =
            *(const float4*)(B + (size_t)(k0 + brw) * N + bcol + bcl);
        __syncthreads();

#pragma unroll
        for (int kk = 0; kk < 8; kk++) {
            float ar[8], br[8];
#pragma unroll
            for (int i = 0; i < 8; i++) ar[i] = As[kk][ty + i];
#pragma unroll
            for (int j = 0; j < 8; j++) br[j] = Bs[kk][tx + j];
#pragma unroll
            for (int i = 0; i < 8; i++)
#pragma unroll
                for (int j = 0; j < 8; j++)
                    acc[i][j] = __fmaf_rn(ar[i], br[j], acc[i][j]);
        }
        __syncthreads();
    }

#pragma unroll
    for (int i = 0; i < 8; i++) {
        float4 c0 = make_float4(acc[i][0], acc[i][1], acc[i][2], acc[i][3]);
        float4 c1 = make_float4(acc[i][4], acc[i][5], acc[i][6], acc[i][7]);
        *(float4*)(C + (size_t)(brow + ty + i) * N + bcol + tx)     = c0;
        *(float4*)(C + (size_t)(brow + ty + i) * N + bcol + tx + 4) = c1;
    }
}

// ---------------------------------------------------------------------------
// Cluster helpers
// ---------------------------------------------------------------------------
__device__ __forceinline__ uint32_t smem_u32(const void* p) {
    uint32_t a;
    asm("{ .reg .u64 t; cvta.to.shared.u64 t, %1; cvt.u32.u64 %0, t; }"
        : "=r"(a) : "l"(p));
    return a;
}
__device__ __forceinline__ uint32_t ctarank() {
    uint32_t r; asm("mov.u32 %0, %%cluster_ctarank;" : "=r"(r)); return r;
}
#define CLUSTER_SYNC() do { \
    asm volatile("barrier.cluster.arrive.aligned;" ::: "memory"); \
    asm volatile("barrier.cluster.wait.aligned;"   ::: "memory"); \
} while (0)

// Publish one mask word to all CLUSTER CTAs (own + peers via DSMEM).
__device__ __forceinline__ void publish_word(unsigned* maskArr, int widx,
                                             unsigned bits, uint32_t myrank)
{
    maskArr[widx] = bits;
    uint32_t a = smem_u32(&maskArr[widx]);
#pragma unroll
    for (uint32_t r = 0; r < CLUSTER; r++) {
        if (r == myrank) continue;
        uint32_t pa;
        asm volatile("mapa.shared::cluster.u32 %0, %1, %2;"
                     : "=r"(pa) : "r"(a), "r"(r));
        asm volatile("st.shared::cluster.u32 [%0], %1;"
                     :: "r"(pa), "r"(bits) : "memory");
    }
}

// Warp 0 builds ascending-index list from the 32-word full mask.
__device__ __forceinline__ void build_from_mask(const unsigned* __restrict__ mask,
                                                int* __restrict__ list,
                                                int* __restrict__ cntp)
{
    if ((threadIdx.x >> 5) == 0) {
        int lane = threadIdx.x & 31;
        unsigned bits = mask[lane];
        int c = __popc(bits);
        int inc = c;
#pragma unroll
        for (int d = 1; d < 32; d <<= 1) {
            int n = __shfl_up_sync(0xffffffffu, inc, d);
            if (lane >= d) inc += n;
        }
        int start = inc - c;
        int base = lane << 5;
        while (bits) {
            int bpos = __ffs(bits) - 1;
            bits &= bits - 1;
            list[start++] = base + bpos;
        }
        if (lane == 31) *cntp = inc;
    }
}

// Single gather over this CTA's column segment (sequential adds, exact fp32).
__device__ __forceinline__ float gather1(const float* __restrict__ Mc,
                                         const int* __restrict__ list, int cnt)
{
    float acc = 0.f;
    int k = 0;
    for (; k + 8 <= cnt; k += 8) {
        float r0 = Mc[(size_t)list[k+0] << 10];
        float r1 = Mc[(size_t)list[k+1] << 10];
        float r2 = Mc[(size_t)list[k+2] << 10];
        float r3 = Mc[(size_t)list[k+3] << 10];
        float r4 = Mc[(size_t)list[k+4] << 10];
        float r5 = Mc[(size_t)list[k+5] << 10];
        float r6 = Mc[(size_t)list[k+6] << 10];
        float r7 = Mc[(size_t)list[k+7] << 10];
        acc += r0; acc += r1; acc += r2; acc += r3;
        acc += r4; acc += r5; acc += r6; acc += r7;
    }
    for (; k < cnt; k++) acc += Mc[(size_t)list[k] << 10];
    return acc;
}

// Dual gather: two independent streams interleaved (2x MLP), per-list order
// identical to sequential gather (bit-exact).
__device__ __forceinline__ void dual_gather(
    const float* __restrict__ M0, const int* __restrict__ l0, int c0,
    const float* __restrict__ M1, const int* __restrict__ l1, int c1,
    float& a0, float& a1)
{
    a0 = 0.f; a1 = 0.f;
    int cmin = min(c0, c1);
    int k = 0;
    for (; k + 4 <= cmin; k += 4) {
        float p0 = M0[(size_t)l0[k+0] << 10];
        float p1 = M0[(size_t)l0[k+1] << 10];
        float p2 = M0[(size_t)l0[k+2] << 10];
        float p3 = M0[(size_t)l0[k+3] << 10];
        float q0 = M1[(size_t)l1[k+0] << 10];
        float q1 = M1[(size_t)l1[k+1] << 10];
        float q2 = M1[(size_t)l1[k+2] << 10];
        float q3 = M1[(size_t)l1[k+3] << 10];
        a0 += p0; a0 += p1; a0 += p2; a0 += p3;
        a1 += q0; a1 += q1; a1 += q2; a1 += q3;
    }
    int k0 = k;
    for (; k0 + 8 <= c0; k0 += 8) {
        float r0 = M0[(size_t)l0[k0+0] << 10];
        float r1 = M0[(size_t)l0[k0+1] << 10];
        float r2 = M0[(size_t)l0[k0+2] << 10];
        float r3 = M0[(size_t)l0[k0+3] << 10];
        float r4 = M0[(size_t)l0[k0+4] << 10];
        float r5 = M0[(size_t)l0[k0+5] << 10];
        float r6 = M0[(size_t)l0[k0+6] << 10];
        float r7 = M0[(size_t)l0[k0+7] << 10];
        a0 += r0; a0 += r1; a0 += r2; a0 += r3;
        a0 += r4; a0 += r5; a0 += r6; a0 += r7;
    }
    for (; k0 < c0; k0++) a0 += M0[(size_t)l0[k0] << 10];
    int k1 = k;
    for (; k1 + 8 <= c1; k1 += 8) {
        float r0 = M1[(size_t)l1[k1+0] << 10];
        float r1 = M1[(size_t)l1[k1+1] << 10];
        float r2 = M1[(size_t)l1[k1+2] << 10];
        float r3 = M1[(size_t)l1[k1+3] << 10];
        float r4 = M1[(size_t)l1[k1+4] << 10];
        float r5 = M1[(size_t)l1[k1+5] << 10];
        float r6 = M1[(size_t)l1[k1+6] << 10];
        float r7 = M1[(size_t)l1[k1+7] << 10];
        a1 += r0; a1 += r1; a1 += r2; a1 += r3;
        a1 += r4; a1 += r5; a1 += r6; a1 += r7;
    }
    for (; k1 < c1; k1++) a1 += M1[(size_t)l1[k1] << 10];
}

// LIF update, FMA-contracted (bit-exact vs reference).
__device__ __forceinline__ void lif_update(float cur, float pot, float h, float rec,
                                           float& ncur, float& npot, float& spk)
{
    float x = __fadd_rn(pot, -1.0f);
    spk = (x > 0.f) ? 1.f : 0.f;
    float active = __fadd_rn(1.0f, -spk);
    ncur = __fadd_rn(__fmaf_rn(ALPHA, cur, h), rec);
    npot = __fmul_rn(__fmaf_rn(BETA, pot, ncur), active);
}

// ---------------------------------------------------------------------------
// Clustered persistent scan: cluster of 4 CTAs per batch row, each CTA owns
// 256 columns (1 per thread). Spike masks exchanged via DSMEM per step.
// ---------------------------------------------------------------------------
__global__ __launch_bounds__(NTS, 5) __cluster_dims__(CLUSTER, 1, 1)
void snn_scan_kernel(
    const float* __restrict__ R0, const float* __restrict__ W1,
    const float* __restrict__ R1,
    float* __restrict__ s1g, float* __restrict__ s2g,
    float* __restrict__ v1g, float* __restrict__ v2g)
{
    __shared__ unsigned mask1[Hn / 32];   // 32 words = full 1024-bit mask
    __shared__ unsigned mask2[Hn / 32];
    __shared__ int list1[Hn];
    __shared__ int list2[Hn];
    __shared__ int cnt1s, cnt2s;

    int tid  = threadIdx.x;
    int lane = tid & 31;
    int wid  = tid >> 5;          // 0..7
    uint32_t q = ctarank();       // column quarter 0..3
    int b = blockIdx.x / CLUSTER;
    int colg = (int)q * CSEG + tid;

    const float* R0c = R0 + colg;
    const float* R1c = R1 + colg;
    const float* W1c = W1 + colg;
    const float* h1c = g_H1 + (size_t)b * Tn * Hn + colg;
    size_t obase = (size_t)b * Tn * Hn + colg;

    float cur1 = 0.f, pot1 = 0.f, spk1 = 0.f;
    float cur2 = 0.f, pot2 = 0.f, spk2 = 0.f;

    for (int t = 0; t < Tn; t++) {
        float h1 = h1c[(size_t)t * Hn];

        float rec1 = 0.f, rec2 = 0.f;
        if (t > 0) {
            int c1 = cnt1s, c2 = cnt2s;
            dual_gather(R0c, list1, c1, R1c, list2, c2, rec1, rec2);
        }

        // ---- layer 1 update ----
        float ncur, npot;
        lif_update(cur1, pot1, h1, rec1, ncur, npot, spk1);
        cur1 = ncur; pot1 = npot;
        v1g[obase + (size_t)t * Hn] = pot1;
        s1g[obase + (size_t)t * Hn] = spk1;

        unsigned bits1 = __ballot_sync(0xffffffffu, spk1 != 0.f);
        if (lane == 0) publish_word(mask1, (int)q * 8 + wid, bits1, q);

        CLUSTER_SYNC();                    // mask1 complete everywhere
        build_from_mask(mask1, list1, &cnt1s);
        __syncthreads();

        // ---- layer 2: h2 = s1[t] @ W1 ----
        float h2 = gather1(W1c, list1, cnt1s);

        lif_update(cur2, pot2, h2, rec2, ncur, npot, spk2);
        cur2 = ncur; pot2 = npot;
        v2g[obase + (size_t)t * Hn] = pot2;
        s2g[obase + (size_t)t * Hn] = spk2;

        unsigned bits2 = __ballot_sync(0xffffffffu, spk2 != 0.f);
        if (lane == 0) publish_word(mask2, (int)q * 8 + wid, bits2, q);

        CLUSTER_SYNC();                    // mask2 complete; list2 safe to rebuild
        build_from_mask(mask2, list2, &cnt2s);
        __syncthreads();
    }
}

// ---------------------------------------------------------------------------
// Readout (separate kernel, reads s2 from global). Bit-fine: terminal output.
// ---------------------------------------------------------------------------
__global__ __launch_bounds__(256) void readout_kernel(
    const float* __restrict__ s2, const float* __restrict__ Wout,
    float* __restrict__ out)
{
    int b = blockIdx.x;
    int lane = threadIdx.x & 31;
    int w = threadIdx.x >> 5;   // 0..7

    float wreg[32];
#pragma unroll
    for (int k = 0; k < 32; k++) wreg[k] = Wout[(size_t)(lane + 32 * k) * On + w];

    if (threadIdx.x < On) out[(size_t)b * (Tn + 1) * On + threadIdx.x] = 0.f;

    float cur = 0.f, pot = 0.f;
    for (int t = 0; t < Tn; t++) {
        const float* srow = s2 + ((size_t)b * Tn + t) * Hn;
        float hsum = 0.f;
#pragma unroll
        for (int k = 0; k < 32; k++) hsum += srow[lane + 32 * k] * wreg[k];
#pragma unroll
        for (int off = 16; off; off >>= 1)
            hsum += __shfl_down_sync(0xffffffffu, hsum, off);
        hsum = __shfl_sync(0xffffffffu, hsum, 0);

        cur = __fmaf_rn(ALPHA, cur, hsum);
        pot = __fmaf_rn(BETA, pot, cur);
        if (lane == 0) out[(size_t)b * (Tn + 1) * On + (size_t)(t + 1) * On + w] = pot;
    }
}

extern "C" void kernel_launch(void* const* d_in, const int* in_sizes, int n_in,
                              void* d_out, int out_size)
{
    const float* inputs = (const float*)d_in[0];
    const float* W0     = (const float*)d_in[1];
    const float* W1     = (const float*)d_in[2];
    const float* R0     = (const float*)d_in[3];
    const float* R1     = (const float*)d_in[4];
    const float* Wout   = (const float*)d_in[5];

    float* out = (float*)d_out;
    float* s1 = out + S1_OFF;
    float* s2 = out + S2_OFF;
    float* v1 = out + V1_OFF;
    float* v2 = out + V2_OFF;

    float* h1ptr = nullptr;
    cudaGetSymbolAddress((void**)&h1ptr, g_H1);

    // H1 = inputs @ W0
    {
        dim3 grid(Hn / 128, (Bsz * Tn) / 128);
        sgemm_kernel<<<grid, 256>>>(inputs, W0, h1ptr, Bsz * Tn, Hn, Fn);
    }

    // Clustered persistent scan: 256 batches x 4 CTAs.
    snn_scan_kernel<<<Bsz * CLUSTER, NTS>>>(R0, W1, R1, s1, s2, v1, v2);

    // Readout
    readout_kernel<<<Bsz, 256>>>(s2, Wout, out);
}

// round 6
// speedup vs baseline: 1.4966x; 1.4966x over previous
#include <cuda_runtime.h>

#define Bsz 256
#define Tn  100
#define Fn  256
#define Hn  1024
#define On  8
#define NT  512   // scan threads per block

#define ALPHA 0.9048374180359595f   // exp(-0.001/0.01)
#define BETA  0.8187307530779818f   // exp(-0.001/0.005)

// Output layout: out [B,T+1,O], s1 [B,T,H], s2 [B,T,H], v1 [B,T,H], v2 [B,T,H]
#define S1_OFF  (Bsz*(Tn+1)*On)
#define S2_OFF  (S1_OFF + Bsz*Tn*Hn)
#define V1_OFF  (S2_OFF + Bsz*Tn*Hn)
#define V2_OFF  (V1_OFF + Bsz*Tn*Hn)

__device__ float g_H1[(size_t)Bsz * Tn * Hn];   // inputs @ W0

// ---------------------------------------------------------------------------
// fp32 SGEMM (sequential-k FFMA chain, bit-matches reference association).
// Already at ~39 TF/s fp32 — at the FMA-pipe roofline; leave untouched.
// ---------------------------------------------------------------------------
__global__ __launch_bounds__(256) void sgemm_kernel(
    const float* __restrict__ A, const float* __restrict__ B,
    float* __restrict__ C, int M, int N, int K)
{
    __shared__ float As[8][128];
    __shared__ float Bs[8][128];

    int tid  = threadIdx.x;
    int brow = blockIdx.y * 128;
    int bcol = blockIdx.x * 128;

    int arow = tid >> 1;
    int acol = (tid & 1) << 2;
    int brw  = tid >> 5;
    int bcl  = (tid & 31) << 2;
    int ty = (tid >> 4) << 3;
    int tx = (tid & 15) << 3;

    float acc[8][8];
#pragma unroll
    for (int i = 0; i < 8; i++)
#pragma unroll
        for (int j = 0; j < 8; j++) acc[i][j] = 0.f;

    for (int k0 = 0; k0 < K; k0 += 8) {
        float4 a4 = *(const float4*)(A + (size_t)(brow + arow) * K + k0 + acol);
        As[acol + 0][arow] = a4.x;
        As[acol + 1][arow] = a4.y;
        As[acol + 2][arow] = a4.z;
        As[acol + 3][arow] = a4.w;
        *(float4*)&Bs[brw][bcl] =
            *(const float4*)(B + (size_t)(k0 + brw) * N + bcol + bcl);
        __syncthreads();

#pragma unroll
        for (int kk = 0; kk < 8; kk++) {
            float ar[8], br[8];
#pragma unroll
            for (int i = 0; i < 8; i++) ar[i] = As[kk][ty + i];
#pragma unroll
            for (int j = 0; j < 8; j++) br[j] = Bs[kk][tx + j];
#pragma unroll
            for (int i = 0; i < 8; i++)
#pragma unroll
                for (int j = 0; j < 8; j++)
                    acc[i][j] = __fmaf_rn(ar[i], br[j], acc[i][j]);
        }
        __syncthreads();
    }

#pragma unroll
    for (int i = 0; i < 8; i++) {
        float4 c0 = make_float4(acc[i][0], acc[i][1], acc[i][2], acc[i][3]);
        float4 c1 = make_float4(acc[i][4], acc[i][5], acc[i][6], acc[i][7]);
        *(float4*)(C + (size_t)(brow + ty + i) * N + bcol + tx)     = c0;
        *(float4*)(C + (size_t)(brow + ty + i) * N + bcol + tx + 4) = c1;
    }
}

// ---------------------------------------------------------------------------
// Deterministic compact ascending-index list from per-thread float2 spikes.
// NT=512 threads, <=2 candidates each, 16-warp scan. Ends synced.
// ---------------------------------------------------------------------------
__device__ __forceinline__ int build_list2(float2 s, int* __restrict__ list,
                                           int* __restrict__ wscan)
{
    int tid  = threadIdx.x;
    int lane = tid & 31;
    int wid  = tid >> 5;

    int idx[2];
    int c = 0;
    int base = tid << 1;
    if (s.x != 0.f) idx[c++] = base;
    if (s.y != 0.f) idx[c++] = base + 1;

    int inc = c;
#pragma unroll
    for (int d = 1; d < 32; d <<= 1) {
        int n = __shfl_up_sync(0xffffffffu, inc, d);
        if (lane >= d) inc += n;
    }
    if (lane == 31) wscan[wid] = inc;
    __syncthreads();
    if (tid == 0) {
        int run = 0;
#pragma unroll
        for (int w = 0; w < 16; w++) { int v = wscan[w]; wscan[w] = run; run += v; }
        wscan[16] = run;
    }
    __syncthreads();
    int start = wscan[wid] + inc - c;
    if (c > 0) list[start] = idx[0];
    if (c > 1) list[start + 1] = idx[1];
    int total = wscan[16];
    __syncthreads();
    return total;
}

#define ACC2(a, r) { (a).x += (r).x; (a).y += (r).y; }
#define ROW2(M, k) (((const float2*)((M) + ((size_t)(k) << 10)))[tid])

// ---------------------------------------------------------------------------
// Triple gather, one phase: streams A=W1 and B=R0 share listL (count cL),
// stream C=R1 uses listM (count cM). All three interleaved for max MLP.
// Per-stream adds are in ascending list order -> bit-exact vs sequential.
// ---------------------------------------------------------------------------
__device__ __forceinline__ void triple_gather2(
    const float* __restrict__ MA, const float* __restrict__ MB,
    const int* __restrict__ listL, int cL,
    const float* __restrict__ MC,
    const int* __restrict__ listM, int cM,
    float2& aA, float2& aB, float2& aC)
{
    int tid = threadIdx.x;
    aA = make_float2(0.f, 0.f);
    aB = make_float2(0.f, 0.f);
    aC = make_float2(0.f, 0.f);

    int cmin = min(cL, cM);
    int k = 0;
    // Common section: 12 loads in flight (4 per stream).
    for (; k + 4 <= cmin; k += 4) {
        int i0 = listL[k+0], i1 = listL[k+1], i2 = listL[k+2], i3 = listL[k+3];
        int j0 = listM[k+0], j1 = listM[k+1], j2 = listM[k+2], j3 = listM[k+3];
        float2 a0 = ROW2(MA, i0); float2 a1 = ROW2(MA, i1);
        float2 a2 = ROW2(MA, i2); float2 a3 = ROW2(MA, i3);
        float2 b0 = ROW2(MB, i0); float2 b1 = ROW2(MB, i1);
        float2 b2 = ROW2(MB, i2); float2 b3 = ROW2(MB, i3);
        float2 c0 = ROW2(MC, j0); float2 c1 = ROW2(MC, j1);
        float2 c2 = ROW2(MC, j2); float2 c3 = ROW2(MC, j3);
        ACC2(aA, a0); ACC2(aA, a1); ACC2(aA, a2); ACC2(aA, a3);
        ACC2(aB, b0); ACC2(aB, b1); ACC2(aB, b2); ACC2(aB, b3);
        ACC2(aC, c0); ACC2(aC, c1); ACC2(aC, c2); ACC2(aC, c3);
    }
    // Remainder of the shared list (A+B dual, 8 loads in flight).
    int kl = k;
    for (; kl + 4 <= cL; kl += 4) {
        int i0 = listL[kl+0], i1 = listL[kl+1], i2 = listL[kl+2], i3 = listL[kl+3];
        float2 a0 = ROW2(MA, i0); float2 a1 = ROW2(MA, i1);
        float2 a2 = ROW2(MA, i2); float2 a3 = ROW2(MA, i3);
        float2 b0 = ROW2(MB, i0); float2 b1 = ROW2(MB, i1);
        float2 b2 = ROW2(MB, i2); float2 b3 = ROW2(MB, i3);
        ACC2(aA, a0); ACC2(aA, a1); ACC2(aA, a2); ACC2(aA, a3);
        ACC2(aB, b0); ACC2(aB, b1); ACC2(aB, b2); ACC2(aB, b3);
    }
    for (; kl < cL; kl++) {
        int i = listL[kl];
        float2 a = ROW2(MA, i); float2 b = ROW2(MB, i);
        ACC2(aA, a); ACC2(aB, b);
    }
    // Remainder of stream C (unroll 8).
    int km = k;
    for (; km + 8 <= cM; km += 8) {
        float2 r0 = ROW2(MC, listM[km+0]); float2 r1 = ROW2(MC, listM[km+1]);
        float2 r2 = ROW2(MC, listM[km+2]); float2 r3 = ROW2(MC, listM[km+3]);
        float2 r4 = ROW2(MC, listM[km+4]); float2 r5 = ROW2(MC, listM[km+5]);
        float2 r6 = ROW2(MC, listM[km+6]); float2 r7 = ROW2(MC, listM[km+7]);
        ACC2(aC, r0); ACC2(aC, r1); ACC2(aC, r2); ACC2(aC, r3);
        ACC2(aC, r4); ACC2(aC, r5); ACC2(aC, r6); ACC2(aC, r7);
    }
    for (; km < cM; km++) { float2 r = ROW2(MC, listM[km]); ACC2(aC, r); }
}

// LIF update, FMA-contracted (bit-exact vs reference).
__device__ __forceinline__ void lif_update(float cur, float pot, float h, float rec,
                                           float& ncur, float& npot, float& spk)
{
    float x = __fadd_rn(pot, -1.0f);
    spk = (x > 0.f) ? 1.f : 0.f;
    float active = __fadd_rn(1.0f, -spk);
    ncur = __fadd_rn(__fmaf_rn(ALPHA, cur, h), rec);
    npot = __fmul_rn(__fmaf_rn(BETA, pot, ncur), active);
}

__device__ __forceinline__ void lif_update2(float2 cur, float2 pot, float2 h, float2 rec,
                                            float2& ncur, float2& npot, float2& spk)
{
    lif_update(cur.x, pot.x, h.x, rec.x, ncur.x, npot.x, spk.x);
    lif_update(cur.y, pot.y, h.y, rec.y, ncur.y, npot.y, spk.y);
}

// ---------------------------------------------------------------------------
// Persistent fused scan, ONE gather phase per step:
//   update1 -> build list1(spk1[t]) -> triple gather
//   (h2=W1@l1, rec1'=R0@l1, rec2=R1@l2(spk2[t-1])) -> update2 -> build list2.
// ---------------------------------------------------------------------------
__global__ __launch_bounds__(NT) void snn_scan_kernel(
    const float* __restrict__ R0, const float* __restrict__ W1,
    const float* __restrict__ R1, const float* __restrict__ Wout,
    float* __restrict__ out,
    float* __restrict__ s1g, float* __restrict__ s2g,
    float* __restrict__ v1g, float* __restrict__ v2g)
{
    __shared__ float sWout[Hn * On];   // 32 KB
    __shared__ int   list1[Hn];
    __shared__ int   list2[Hn];
    __shared__ int   wscan[17];
    __shared__ float wsum[16][On];

    int b    = blockIdx.x;
    int tid  = threadIdx.x;
    int lane = tid & 31;
    int wid  = tid >> 5;

#pragma unroll
    for (int i = 0; i < 4; i++)
        ((float4*)sWout)[tid + NT * i] = ((const float4*)Wout)[tid + NT * i];

    if (tid < On) out[(size_t)b * (Tn + 1) * On + tid] = 0.f;

    float2 z = make_float2(0.f, 0.f);
    float2 cur1 = z, pot1 = z, spk1 = z;
    float2 cur2 = z, pot2 = z, spk2 = z;
    float2 rec1 = z;              // R0@spk1[t-1], carried across steps
    int c2 = 0;                   // list2 count (spk2[t-1])
    float cur_ro = 0.f, pot_ro = 0.f;

    const float* h1base = g_H1 + (size_t)b * Tn * Hn;
    size_t rowbase = (size_t)b * Tn * Hn;

    __syncthreads();

    for (int t = 0; t < Tn; t++) {
        // ---- layer 1 update (rec1 precomputed last step) ----
        float2 h1 = ((const float2*)(h1base + (size_t)t * Hn))[tid];
        float2 ncur, npot;
        lif_update2(cur1, pot1, h1, rec1, ncur, npot, spk1);
        cur1 = ncur; pot1 = npot;
        ((float2*)(v1g + rowbase + (size_t)t * Hn))[tid] = pot1;
        ((float2*)(s1g + rowbase + (size_t)t * Hn))[tid] = spk1;

        // ---- build list1 from spk1[t] (internal syncs) ----
        int c1 = build_list2(spk1, list1, wscan);

        // ---- single triple-gather phase ----
        float2 h2, rec1n, rec2;
        triple_gather2(W1, R0, list1, c1, R1, list2, c2, h2, rec1n, rec2);
        rec1 = rec1n;

        // ---- layer 2 update ----
        lif_update2(cur2, pot2, h2, rec2, ncur, npot, spk2);
        cur2 = ncur; pot2 = npot;
        ((float2*)(v2g + rowbase + (size_t)t * Hn))[tid] = pot2;
        ((float2*)(s2g + rowbase + (size_t)t * Hn))[tid] = spk2;

        // ---- readout: h_ro = s2[t] @ Wout, leaky double integrator ----
        float pacc[On];
#pragma unroll
        for (int o = 0; o < On; o++) pacc[o] = 0.f;
        int base = tid << 1;
        if (spk2.x != 0.f) {
#pragma unroll
            for (int o = 0; o < On; o++) pacc[o] += sWout[(base + 0) * On + o];
        }
        if (spk2.y != 0.f) {
#pragma unroll
            for (int o = 0; o < On; o++) pacc[o] += sWout[(base + 1) * On + o];
        }
#pragma unroll
        for (int o = 0; o < On; o++) {
            float v = pacc[o];
#pragma unroll
            for (int off = 16; off; off >>= 1)
                v += __shfl_down_sync(0xffffffffu, v, off);
            if (lane == 0) wsum[wid][o] = v;
        }
        __syncthreads();
        if (tid < On) {
            float tot = 0.f;
#pragma unroll
            for (int w = 0; w < 16; w++) tot += wsum[w][tid];
            cur_ro = __fmaf_rn(ALPHA, cur_ro, tot);
            pot_ro = __fmaf_rn(BETA, pot_ro, cur_ro);
            out[(size_t)b * (Tn + 1) * On + (size_t)(t + 1) * On + tid] = pot_ro;
        }
        __syncthreads();

        // ---- build list2 from spk2[t] for next step's gather ----
        c2 = build_list2(spk2, list2, wscan);
    }
}

extern "C" void kernel_launch(void* const* d_in, const int* in_sizes, int n_in,
                              void* d_out, int out_size)
{
    const float* inputs = (const float*)d_in[0];
    const float* W0     = (const float*)d_in[1];
    const float* W1     = (const float*)d_in[2];
    const float* R0     = (const float*)d_in[3];
    const float* R1     = (const float*)d_in[4];
    const float* Wout   = (const float*)d_in[5];

    float* out = (float*)d_out;
    float* s1 = out + S1_OFF;
    float* s2 = out + S2_OFF;
    float* v1 = out + V1_OFF;
    float* v2 = out + V2_OFF;

    float* h1ptr = nullptr;
    cudaGetSymbolAddress((void**)&h1ptr, g_H1);

    // H1 = inputs @ W0
    {
        dim3 grid(Hn / 128, (Bsz * Tn) / 128);
        sgemm_kernel<<<grid, 256>>>(inputs, W0, h1ptr, Bsz * Tn, Hn, Fn);
    }

    // Fused persistent scan: one block per batch row, one gather phase/step.
    snn_scan_kernel<<<Bsz, NT>>>(R0, W1, R1, Wout, out, s1, s2, v1, v2);
}